// round 6
// baseline (speedup 1.0000x reference)
#include <cuda_runtime.h>
#include <cuda_bf16.h>
#include <cuda_fp16.h>
#include <math.h>
#include <stdint.h>

#define B_    8
#define D_    512
#define L_    1024
#define NPOS  8192
#define KCB   8192
#define EDIM  512
#define SEMD  256
#define NQ    4194304

typedef unsigned long long ull;

// ---------------- scratch ----------------
static __device__ float          g_Zn [NPOS * EDIM];
static __device__ __nv_bfloat16  g_ZnB[NPOS * EDIM];
static __device__ float          g_En [KCB * EDIM];
static __device__ __nv_bfloat16  g_EnB[KCB * EDIM];
static __device__ float g_psum[8][NPOS];
static __device__ float g_invk[NPOS], g_invg[NPOS];
static __device__ float g_akd[NPOS],  g_agan[NPOS];
static __device__ float g_bkd[KCB],   g_bgan[KCB];
static __device__ __half g_Dh[(size_t)NPOS * KCB];   // approx dsum fp16, [n][k]
static __device__ unsigned g_keyu[NPOS];
static __device__ float g_Spt[2][64];
static __device__ int   g_idx[NPOS];

// ---------------- helpers ----------------
__device__ __forceinline__ float wsum(float s) {
#pragma unroll
    for (int o = 16; o > 0; o >>= 1) s += __shfl_xor_sync(0xffffffffu, s, o);
    return s;
}
__device__ __forceinline__ unsigned s2u(const void* p) {
    unsigned a;
    asm("{ .reg .u64 t; cvta.to.shared.u64 t, %1; cvt.u32.u64 %0, t; }" : "=r"(a) : "l"(p));
    return a;
}
__device__ __forceinline__ void cpasync16(unsigned s, const void* g) {
    asm volatile("cp.async.cg.shared.global [%0], [%1], 16;\n" :: "r"(s), "l"(g));
}
__device__ __forceinline__ void ldsm4(unsigned addr, unsigned &r0, unsigned &r1,
                                      unsigned &r2, unsigned &r3) {
    asm volatile("ldmatrix.sync.aligned.m8n8.x4.shared.b16 {%0,%1,%2,%3}, [%4];"
                 : "=r"(r0), "=r"(r1), "=r"(r2), "=r"(r3) : "r"(addr));
}
__device__ __forceinline__ void mma_bf16(float* c, unsigned a0, unsigned a1, unsigned a2,
                                         unsigned a3, unsigned b0, unsigned b1) {
    asm volatile("mma.sync.aligned.m16n8k16.row.col.f32.bf16.bf16.f32 "
                 "{%0,%1,%2,%3}, {%4,%5,%6,%7}, {%8,%9}, {%0,%1,%2,%3};"
                 : "+f"(c[0]), "+f"(c[1]), "+f"(c[2]), "+f"(c[3])
                 : "r"(a0), "r"(a1), "r"(a2), "r"(a3), "r"(b0), "r"(b1));
}

// ---------------- 1. normalize embeddings ----------------
__global__ void k_emb(const float* __restrict__ ekd, const float* __restrict__ egan) {
    int w = threadIdx.x >> 5, lane = threadIdx.x & 31;
    int k = blockIdx.x * 8 + w;
#pragma unroll
    for (int h = 0; h < 2; ++h) {
        const float* p = (h ? egan : ekd) + (size_t)k * SEMD;
        float v[8]; float s = 0.f;
#pragma unroll
        for (int j = 0; j < 8; ++j) { v[j] = p[lane + j * 32]; s += v[j] * v[j]; }
        s = wsum(s);
        float inv = 1.f / fmaxf(sqrtf(s), 1e-12f);
        float t = 0.f;
#pragma unroll
        for (int j = 0; j < 8; ++j) {
            float nv = v[j] * inv;
            size_t o = (size_t)k * EDIM + h * SEMD + lane + j * 32;
            g_En[o] = nv;
            g_EnB[o] = __float2bfloat16_rn(nv);
            t += nv * nv;
        }
        t = wsum(t);
        if (lane == 0) { if (h) g_bgan[k] = t; else g_bkd[k] = t; }
    }
}

// ---------------- 2. z sumsq partials ----------------
__global__ void k_zsumsq(const float* __restrict__ z) {
    int l = blockIdx.x * 256 + threadIdx.x, b = blockIdx.y, seg = blockIdx.z;
    const float* p = z + (size_t)b * D_ * L_ + (size_t)seg * 64 * L_ + l;
    float s = 0.f;
#pragma unroll 8
    for (int d = 0; d < 64; ++d) { float v = p[(size_t)d * L_]; s += v * v; }
    g_psum[seg][b * L_ + l] = s;
}

// ---------------- 3. finalize norms + init key/S ----------------
__global__ void k_zfinal() {
    int n = blockIdx.x * 256 + threadIdx.x;
    float s = g_psum[0][n] + g_psum[1][n] + g_psum[2][n] + g_psum[3][n];
    float inv = 1.f / fmaxf(sqrtf(s), 1e-12f);
    g_invk[n] = inv; g_akd[n] = s * inv * inv;
    float s2 = g_psum[4][n] + g_psum[5][n] + g_psum[6][n] + g_psum[7][n];
    float inv2 = 1.f / fmaxf(sqrtf(s2), 1e-12f);
    g_invg[n] = inv2; g_agan[n] = s2 * inv2 * inv2;
    g_keyu[n] = 0xFFFFFFFFu;
    if (n < 128) g_Spt[n >> 6][n & 63] = 0.f;
}

// ---------------- 4. transpose + normalize z into (n, e) ----------------
__global__ void k_ztrans(const float* __restrict__ z) {
    __shared__ float s[32][33];
    int d0 = blockIdx.x * 32, l0 = blockIdx.y * 32, b = blockIdx.z;
    int tx = threadIdx.x, ty = threadIdx.y;
#pragma unroll
    for (int q = 0; q < 4; ++q) {
        int dy = ty * 4 + q;
        s[dy][tx] = z[((size_t)b * D_ + d0 + dy) * L_ + l0 + tx];
    }
    __syncthreads();
    bool kdh = (d0 < SEMD);
#pragma unroll
    for (int q = 0; q < 4; ++q) {
        int lr = ty * 4 + q;
        int n = b * L_ + l0 + lr;
        float inv = kdh ? g_invk[n] : g_invg[n];
        float v = s[tx][lr] * inv;
        size_t o = (size_t)n * EDIM + d0 + tx;
        g_Zn[o] = v;
        g_ZnB[o] = __float2bfloat16_rn(v);
    }
}

// ---------------- 5. bf16 mma GEMM 128x128, 3-stage pipeline ----------------
// 8 warps = 4(wm) x 2(wn); warp tile 32x64; chunk = 32 e; stage = A(10240B)+B(10240B)
#define STG 20480
__global__ void __launch_bounds__(256, 1) k_gemm_mma() {
    extern __shared__ char dsm[];
    __shared__ float sRed[2][8];

    const int tid = threadIdx.x, lane = tid & 31, w = tid >> 5;
    const int kt = blockIdx.x, rt = blockIdx.y;
    const int row0 = rt * 128, k0 = kt * 128;
    const int wm = w & 3, wn = w >> 2;

    unsigned sbase = s2u(dsm);

    auto load_chunk = [&](int c, int st) {
        int e0 = c * 32;
        const __nv_bfloat16* Ag = g_ZnB + (size_t)row0 * EDIM + e0;
        const __nv_bfloat16* Bg = g_EnB + (size_t)k0 * EDIM + e0;
        unsigned ab = sbase + st * STG;
        unsigned bb = ab + 10240;
#pragma unroll
        for (int i = 0; i < 2; ++i) {
            int q = tid + i * 256; int r = q >> 2, ch = q & 3;
            cpasync16(ab + r * 80 + ch * 16, Ag + (size_t)r * EDIM + ch * 8);
        }
#pragma unroll
        for (int i = 0; i < 2; ++i) {
            int q = tid + i * 256; int r = q >> 2, ch = q & 3;
            cpasync16(bb + r * 80 + ch * 16, Bg + (size_t)r * EDIM + ch * 8);
        }
        asm volatile("cp.async.commit_group;" ::: "memory");
    };

    float acck[2][8][4], accg[2][8][4];
#pragma unroll
    for (int t = 0; t < 2; ++t)
#pragma unroll
        for (int j = 0; j < 8; ++j)
#pragma unroll
            for (int q = 0; q < 4; ++q) { acck[t][j][q] = 0.f; accg[t][j][q] = 0.f; }

    const int lr = lane & 7, lg = lane >> 3;

    auto compute = [&](int st, float (&acc)[2][8][4]) {
        unsigned ab = sbase + st * STG;
        unsigned bb = ab + 10240;
#pragma unroll
        for (int s = 0; s < 2; ++s) {
            unsigned a0[2], a1[2], a2[2], a3[2];
#pragma unroll
            for (int t = 0; t < 2; ++t) {
                int row = wm * 32 + t * 16 + lr + 8 * (lg & 1);
                int col = s * 16 + 8 * (lg >> 1);
                ldsm4(ab + row * 80 + col * 2, a0[t], a1[t], a2[t], a3[t]);
            }
            unsigned bf[8][2];
#pragma unroll
            for (int jp = 0; jp < 4; ++jp) {
                int brow = wn * 64 + (jp * 2 + (lg >> 1)) * 8 + lr;
                int bcol = s * 16 + 8 * (lg & 1);
                ldsm4(bb + brow * 80 + bcol * 2,
                      bf[jp * 2][0], bf[jp * 2][1], bf[jp * 2 + 1][0], bf[jp * 2 + 1][1]);
            }
#pragma unroll
            for (int t = 0; t < 2; ++t)
#pragma unroll
                for (int j = 0; j < 8; ++j)
                    mma_bf16(acc[t][j], a0[t], a1[t], a2[t], a3[t], bf[j][0], bf[j][1]);
        }
    };

    load_chunk(0, 0);
    load_chunk(1, 1);
    load_chunk(2, 2);
#pragma unroll 1
    for (int c = 0; c < 16; ++c) {
        asm volatile("cp.async.wait_group 2;" ::: "memory");
        __syncthreads();
        int st = c % 3;
        if (c < 8) compute(st, acck);
        else       compute(st, accg);
        __syncthreads();
        if (c + 3 < 16) load_chunk(c + 3, st);
    }

    // ---- epilogue ----
    const int lq = lane >> 2, lp = lane & 3;
    const int kb = k0 + wn * 64 + lp * 2;
    float Sk = 0.f, Sg = 0.f;
#pragma unroll
    for (int t = 0; t < 2; ++t) {
        int rA = row0 + wm * 32 + t * 16 + lq;
#pragma unroll
        for (int h = 0; h < 2; ++h) {
            int rr = rA + 8 * h;
            float ak_ = g_akd[rr], ag_ = g_agan[rr];
            unsigned rmin = 0xFFFFFFFFu;
            __half* drow = g_Dh + (size_t)rr * KCB;
#pragma unroll
            for (int j = 0; j < 8; ++j) {
                int kk = kb + j * 8;
                float dk0 = (ak_ + g_bkd[kk])     - 2.f * acck[t][j][2 * h];
                float dg0 = (ag_ + g_bgan[kk])    - 2.f * accg[t][j][2 * h];
                float dk1 = (ak_ + g_bkd[kk + 1]) - 2.f * acck[t][j][2 * h + 1];
                float dg1 = (ag_ + g_bgan[kk + 1])- 2.f * accg[t][j][2 * h + 1];
                Sk = fmaf(dk0, dk0, Sk); Sk = fmaf(dk1, dk1, Sk);
                Sg = fmaf(dg0, dg0, Sg); Sg = fmaf(dg1, dg1, Sg);
                float d0 = dk0 + dg0, d1 = dk1 + dg1;
                rmin = min(rmin, min(__float_as_uint(d0), __float_as_uint(d1)));
                *(__half2*)(drow + kk) = __floats2half2_rn(d0, d1);
            }
            rmin = min(rmin, __shfl_xor_sync(0xffffffffu, rmin, 1));
            rmin = min(rmin, __shfl_xor_sync(0xffffffffu, rmin, 2));
            if (lp == 0) atomicMin(&g_keyu[rr], rmin);
        }
    }
    Sk = wsum(Sk); Sg = wsum(Sg);
    if (lane == 0) { sRed[0][w] = Sk; sRed[1][w] = Sg; }
    __syncthreads();
    if (tid < 2) {
        float s = 0.f;
#pragma unroll
        for (int i = 0; i < 8; ++i) s += sRed[tid][i];
        atomicAdd(&g_Spt[tid][rt], s);
    }
}

// ---------------- 6. scan + exact rescore (warp per query) ----------------
__global__ void k_scan(float* __restrict__ out) {
    int w = threadIdx.x >> 5, lane = threadIdx.x & 31;
    int n = blockIdx.x * 8 + w;
    float th = __uint_as_float(g_keyu[n]) + 1.5e-2f;
    const __half2* row = (const __half2*)(g_Dh + (size_t)n * KCB);
    int cand[4]; int nc = 0;
#pragma unroll 8
    for (int i = 0; i < 128; ++i) {
        int p = i * 32 + lane;
        float2 fv = __half22float2(row[p]);
        if (fv.x <= th && nc < 4) cand[nc++] = p * 2;
        if (fv.y <= th && nc < 4) cand[nc++] = p * 2 + 1;
    }
    ull bkey = ~0ull;
    float akd = g_akd[n], agn = g_agan[n];
    const float* zr = g_Zn + (size_t)n * EDIM;
    for (int c2 = 0; c2 < nc; ++c2) {
        int k = cand[c2];
        const float* er = g_En + (size_t)k * EDIM;
        float ck = 0.f, cg = 0.f;
        for (int e = 0; e < SEMD; e += 4) {
            float4 zv = *(const float4*)(zr + e);
            float4 ev = *(const float4*)(er + e);
            ck = fmaf(zv.x, ev.x, ck); ck = fmaf(zv.y, ev.y, ck);
            ck = fmaf(zv.z, ev.z, ck); ck = fmaf(zv.w, ev.w, ck);
        }
        for (int e = SEMD; e < EDIM; e += 4) {
            float4 zv = *(const float4*)(zr + e);
            float4 ev = *(const float4*)(er + e);
            cg = fmaf(zv.x, ev.x, cg); cg = fmaf(zv.y, ev.y, cg);
            cg = fmaf(zv.z, ev.z, cg); cg = fmaf(zv.w, ev.w, cg);
        }
        float d = ((akd + g_bkd[k]) - 2.f * ck) + ((agn + g_bgan[k]) - 2.f * cg);
        ull key = ((ull)__float_as_uint(d) << 32) | (unsigned)k;
        if (key < bkey) bkey = key;
    }
#pragma unroll
    for (int o = 16; o > 0; o >>= 1) {
        ull other = __shfl_xor_sync(0xffffffffu, bkey, o);
        if (other < bkey) bkey = other;
    }
    if (lane == 0) {
        int bi = (int)(unsigned)bkey;
        g_idx[n] = bi;
        out[NQ + 2 + n] = (float)bi;
    }
    if (blockIdx.x == 0 && threadIdx.x < 2) {
        float s = 0.f;
        for (int i = 0; i < 64; ++i) s += g_Spt[threadIdx.x][i];
        out[NQ + threadIdx.x] = s * (1.f / 8192.f);
    }
}

// ---------------- 7. z_q gather ----------------
__global__ void k_zq(float* __restrict__ out) {
    int row0 = blockIdx.x * 64;
    int b = row0 >> 10, l0 = row0 & 1023;
    int lq = threadIdx.x & 63, dg = threadIdx.x >> 6;
    int n = row0 + lq;
    int kidx = g_idx[n];
    const float* Erow = g_En + (size_t)kidx * EDIM;
    const float* Zrow = g_Zn + (size_t)n * EDIM;
#pragma unroll 4
    for (int dit = 0; dit < 128; ++dit) {
        int d = dg * 128 + dit;
        float ev = Erow[d];
        float zn = Zrow[d];
        out[((size_t)b * D_ + d) * L_ + l0 + lq] = zn + (ev - zn);
    }
}

extern "C" void kernel_launch(void* const* d_in, const int* in_sizes, int n_in,
                              void* d_out, int out_size) {
    (void)in_sizes; (void)n_in; (void)out_size;
    const float* z    = (const float*)d_in[0];
    const float* ekd  = (const float*)d_in[1];
    const float* egan = (const float*)d_in[2];
    float* out = (float*)d_out;

    static int inited = 0;
    if (!inited) {
        cudaFuncSetAttribute(k_gemm_mma, cudaFuncAttributeMaxDynamicSharedMemorySize, 3 * STG);
        inited = 1;
    }

    k_emb<<<KCB / 8, 256>>>(ekd, egan);
    k_zsumsq<<<dim3(4, 8, 8), 256>>>(z);
    k_zfinal<<<NPOS / 256, 256>>>();
    k_ztrans<<<dim3(16, 32, 8), dim3(32, 8)>>>(z);
    k_gemm_mma<<<dim3(64, 64), 256, 3 * STG>>>();
    k_scan<<<NPOS / 8, 256>>>(out);
    k_zq<<<128, 256>>>(out);
}

// round 7
// speedup vs baseline: 1.1536x; 1.1536x over previous
#include <cuda_runtime.h>
#include <cuda_bf16.h>
#include <cuda_fp16.h>
#include <math.h>
#include <stdint.h>

#define B_    8
#define D_    512
#define L_    1024
#define NPOS  8192
#define KCB   8192
#define EDIM  512
#define SEMD  256
#define NQ    4194304

typedef unsigned long long ull;

// ---------------- scratch ----------------
static __device__ float          g_Zn [NPOS * EDIM];
static __device__ __nv_bfloat16  g_ZnB[NPOS * EDIM];
static __device__ float          g_En [KCB * EDIM];
static __device__ __nv_bfloat16  g_EnB[KCB * EDIM];
static __device__ float g_psum[8][NPOS];
static __device__ float g_invk[NPOS], g_invg[NPOS];
static __device__ float g_akd[NPOS],  g_agan[NPOS];
static __device__ float g_bkd[KCB],   g_bgan[KCB];
static __device__ __half g_Dh[(size_t)NPOS * KCB];   // approx dsum fp16, [n][k]
static __device__ unsigned g_keyu[NPOS];
static __device__ float g_Spt[2][64];
static __device__ int   g_idx[NPOS];

// ---------------- helpers ----------------
__device__ __forceinline__ float wsum(float s) {
#pragma unroll
    for (int o = 16; o > 0; o >>= 1) s += __shfl_xor_sync(0xffffffffu, s, o);
    return s;
}
__device__ __forceinline__ unsigned s2u(const void* p) {
    unsigned a;
    asm("{ .reg .u64 t; cvta.to.shared.u64 t, %1; cvt.u32.u64 %0, t; }" : "=r"(a) : "l"(p));
    return a;
}
__device__ __forceinline__ void cpasync16(unsigned s, const void* g) {
    asm volatile("cp.async.cg.shared.global [%0], [%1], 16;\n" :: "r"(s), "l"(g));
}
__device__ __forceinline__ void ldsm4(unsigned addr, unsigned &r0, unsigned &r1,
                                      unsigned &r2, unsigned &r3) {
    asm volatile("ldmatrix.sync.aligned.m8n8.x4.shared.b16 {%0,%1,%2,%3}, [%4];"
                 : "=r"(r0), "=r"(r1), "=r"(r2), "=r"(r3) : "r"(addr));
}
__device__ __forceinline__ void mma_bf16(float* c, unsigned a0, unsigned a1, unsigned a2,
                                         unsigned a3, unsigned b0, unsigned b1) {
    asm volatile("mma.sync.aligned.m16n8k16.row.col.f32.bf16.bf16.f32 "
                 "{%0,%1,%2,%3}, {%4,%5,%6,%7}, {%8,%9}, {%0,%1,%2,%3};"
                 : "+f"(c[0]), "+f"(c[1]), "+f"(c[2]), "+f"(c[3])
                 : "r"(a0), "r"(a1), "r"(a2), "r"(a3), "r"(b0), "r"(b1));
}

// ---------------- 1. normalize embeddings ----------------
__global__ void k_emb(const float* __restrict__ ekd, const float* __restrict__ egan) {
    int w = threadIdx.x >> 5, lane = threadIdx.x & 31;
    int k = blockIdx.x * 8 + w;
#pragma unroll
    for (int h = 0; h < 2; ++h) {
        const float* p = (h ? egan : ekd) + (size_t)k * SEMD;
        float v[8]; float s = 0.f;
#pragma unroll
        for (int j = 0; j < 8; ++j) { v[j] = p[lane + j * 32]; s += v[j] * v[j]; }
        s = wsum(s);
        float inv = 1.f / fmaxf(sqrtf(s), 1e-12f);
        float t = 0.f;
#pragma unroll
        for (int j = 0; j < 8; ++j) {
            float nv = v[j] * inv;
            size_t o = (size_t)k * EDIM + h * SEMD + lane + j * 32;
            g_En[o] = nv;
            g_EnB[o] = __float2bfloat16_rn(nv);
            t += nv * nv;
        }
        t = wsum(t);
        if (lane == 0) { if (h) g_bgan[k] = t; else g_bkd[k] = t; }
    }
}

// ---------------- 2. z sumsq partials ----------------
__global__ void k_zsumsq(const float* __restrict__ z) {
    int l = blockIdx.x * 256 + threadIdx.x, b = blockIdx.y, seg = blockIdx.z;
    const float* p = z + (size_t)b * D_ * L_ + (size_t)seg * 64 * L_ + l;
    float s = 0.f;
#pragma unroll 8
    for (int d = 0; d < 64; ++d) { float v = p[(size_t)d * L_]; s += v * v; }
    g_psum[seg][b * L_ + l] = s;
}

// ---------------- 3. finalize norms + init key/S ----------------
__global__ void k_zfinal() {
    int n = blockIdx.x * 256 + threadIdx.x;
    float s = g_psum[0][n] + g_psum[1][n] + g_psum[2][n] + g_psum[3][n];
    float inv = 1.f / fmaxf(sqrtf(s), 1e-12f);
    g_invk[n] = inv; g_akd[n] = s * inv * inv;
    float s2 = g_psum[4][n] + g_psum[5][n] + g_psum[6][n] + g_psum[7][n];
    float inv2 = 1.f / fmaxf(sqrtf(s2), 1e-12f);
    g_invg[n] = inv2; g_agan[n] = s2 * inv2 * inv2;
    g_keyu[n] = 0xFFFFFFFFu;
    if (n < 128) g_Spt[n >> 6][n & 63] = 0.f;
}

// ---------------- 4. transpose + normalize z into (n, e) ----------------
__global__ void k_ztrans(const float* __restrict__ z) {
    __shared__ float s[32][33];
    int d0 = blockIdx.x * 32, l0 = blockIdx.y * 32, b = blockIdx.z;
    int tx = threadIdx.x, ty = threadIdx.y;
#pragma unroll
    for (int q = 0; q < 4; ++q) {
        int dy = ty * 4 + q;
        s[dy][tx] = z[((size_t)b * D_ + d0 + dy) * L_ + l0 + tx];
    }
    __syncthreads();
    bool kdh = (d0 < SEMD);
#pragma unroll
    for (int q = 0; q < 4; ++q) {
        int lr = ty * 4 + q;
        int n = b * L_ + l0 + lr;
        float inv = kdh ? g_invk[n] : g_invg[n];
        float v = s[tx][lr] * inv;
        size_t o = (size_t)n * EDIM + d0 + tx;
        g_Zn[o] = v;
        g_ZnB[o] = __float2bfloat16_rn(v);
    }
}

// ---------------- 5. bf16 mma GEMM 128x64, 4-stage, 2 CTAs/SM ----------------
// 8 warps = 4(wm) x 2(wn); warp tile 32x32; chunk = 32 e
// stage = A(128*80=10240B) + B(64*80=5120B) = 15360B; 4 stages = 61440B
#define STG4 15360
__global__ void __launch_bounds__(256, 2) k_gemm_mma() {
    extern __shared__ char dsm[];
    __shared__ float sRed[2][8];

    const int tid = threadIdx.x, lane = tid & 31, w = tid >> 5;
    // L2 supertile swizzle: 256-CTA blocks covering 16 kt x 16 rt
    const int bid = blockIdx.x;
    const int sup = bid >> 8, loc = bid & 255;
    const int kt = ((sup & 7) << 4) | (loc & 15);
    const int rt = ((sup >> 3) << 4) | (loc >> 4);
    const int row0 = rt * 128, k0 = kt * 64;
    const int wm = w & 3, wn = w >> 2;

    unsigned sbase = s2u(dsm);

    auto load_chunk = [&](int c) {
        int st = c & 3;
        int e0 = c * 32;
        const __nv_bfloat16* Ag = g_ZnB + (size_t)row0 * EDIM + e0;
        const __nv_bfloat16* Bg = g_EnB + (size_t)k0 * EDIM + e0;
        unsigned ab = sbase + st * STG4;
        unsigned bb = ab + 10240;
#pragma unroll
        for (int i = 0; i < 2; ++i) {
            int q = tid + i * 256; int r = q >> 2, ch = q & 3;
            cpasync16(ab + r * 80 + ch * 16, Ag + (size_t)r * EDIM + ch * 8);
        }
        { int r = tid >> 2, ch = tid & 3;
          cpasync16(bb + r * 80 + ch * 16, Bg + (size_t)r * EDIM + ch * 8); }
        asm volatile("cp.async.commit_group;" ::: "memory");
    };

    float acck[2][4][4], accg[2][4][4];
#pragma unroll
    for (int t = 0; t < 2; ++t)
#pragma unroll
        for (int j = 0; j < 4; ++j)
#pragma unroll
            for (int q = 0; q < 4; ++q) { acck[t][j][q] = 0.f; accg[t][j][q] = 0.f; }

    const int lr = lane & 7, lg = lane >> 3;

    auto compute = [&](int st, float (&acc)[2][4][4]) {
        unsigned ab = sbase + st * STG4;
        unsigned bb = ab + 10240;
#pragma unroll
        for (int s = 0; s < 2; ++s) {
            unsigned a0[2], a1[2], a2[2], a3[2];
#pragma unroll
            for (int t = 0; t < 2; ++t) {
                int row = wm * 32 + t * 16 + lr + 8 * (lg & 1);
                int col = s * 16 + 8 * (lg >> 1);
                ldsm4(ab + row * 80 + col * 2, a0[t], a1[t], a2[t], a3[t]);
            }
            unsigned bf[4][2];
#pragma unroll
            for (int jp = 0; jp < 2; ++jp) {
                int brow = wn * 32 + (jp * 2 + (lg >> 1)) * 8 + lr;
                int bcol = s * 16 + 8 * (lg & 1);
                ldsm4(bb + brow * 80 + bcol * 2,
                      bf[jp * 2][0], bf[jp * 2][1], bf[jp * 2 + 1][0], bf[jp * 2 + 1][1]);
            }
#pragma unroll
            for (int t = 0; t < 2; ++t)
#pragma unroll
                for (int j = 0; j < 4; ++j)
                    mma_bf16(acc[t][j], a0[t], a1[t], a2[t], a3[t], bf[j][0], bf[j][1]);
        }
    };

    load_chunk(0); load_chunk(1); load_chunk(2);
#pragma unroll 1
    for (int c = 0; c < 16; ++c) {
        asm volatile("cp.async.wait_group 2;" ::: "memory");
        __syncthreads();
        // stage (c+3)&3 == (c-1)&3: all readers passed the barrier above -> safe
        if (c + 3 < 16) load_chunk(c + 3);
        if (c < 8) compute(c & 3, acck);
        else       compute(c & 3, accg);
    }

    // ---- epilogue ----
    const int lq = lane >> 2, lp = lane & 3;
    const int kb = k0 + wn * 32 + lp * 2;
    float Sk = 0.f, Sg = 0.f;
#pragma unroll
    for (int t = 0; t < 2; ++t) {
        int rA = row0 + wm * 32 + t * 16 + lq;
#pragma unroll
        for (int h = 0; h < 2; ++h) {
            int rr = rA + 8 * h;
            float ak_ = g_akd[rr], ag_ = g_agan[rr];
            unsigned rmin = 0xFFFFFFFFu;
            __half* drow = g_Dh + (size_t)rr * KCB;
#pragma unroll
            for (int j = 0; j < 4; ++j) {
                int kk = kb + j * 8;
                float dk0 = (ak_ + g_bkd[kk])      - 2.f * acck[t][j][2 * h];
                float dg0 = (ag_ + g_bgan[kk])     - 2.f * accg[t][j][2 * h];
                float dk1 = (ak_ + g_bkd[kk + 1])  - 2.f * acck[t][j][2 * h + 1];
                float dg1 = (ag_ + g_bgan[kk + 1]) - 2.f * accg[t][j][2 * h + 1];
                Sk = fmaf(dk0, dk0, Sk); Sk = fmaf(dk1, dk1, Sk);
                Sg = fmaf(dg0, dg0, Sg); Sg = fmaf(dg1, dg1, Sg);
                float d0 = dk0 + dg0, d1 = dk1 + dg1;
                rmin = min(rmin, min(__float_as_uint(d0), __float_as_uint(d1)));
                *(__half2*)(drow + kk) = __floats2half2_rn(d0, d1);
            }
            rmin = min(rmin, __shfl_xor_sync(0xffffffffu, rmin, 1));
            rmin = min(rmin, __shfl_xor_sync(0xffffffffu, rmin, 2));
            if (lp == 0) atomicMin(&g_keyu[rr], rmin);
        }
    }
    Sk = wsum(Sk); Sg = wsum(Sg);
    if (lane == 0) { sRed[0][w] = Sk; sRed[1][w] = Sg; }
    __syncthreads();
    if (tid < 2) {
        float s = 0.f;
#pragma unroll
        for (int i = 0; i < 8; ++i) s += sRed[tid][i];
        atomicAdd(&g_Spt[tid][rt], s);
    }
}

// ---------------- 6. scan + exact rescore (warp per query, fp16 D) ----------------
__global__ void k_scan(float* __restrict__ out) {
    int w = threadIdx.x >> 5, lane = threadIdx.x & 31;
    int n = blockIdx.x * 8 + w;
    float th = __uint_as_float(g_keyu[n]) + 1.5e-2f;
    const __half2* row = (const __half2*)(g_Dh + (size_t)n * KCB);
    int cand[4]; int nc = 0;
#pragma unroll 8
    for (int i = 0; i < 128; ++i) {
        int p = i * 32 + lane;
        float2 fv = __half22float2(row[p]);
        if (fv.x <= th && nc < 4) cand[nc++] = p * 2;
        if (fv.y <= th && nc < 4) cand[nc++] = p * 2 + 1;
    }
    ull bkey = ~0ull;
    float akd = g_akd[n], agn = g_agan[n];
    const float* zr = g_Zn + (size_t)n * EDIM;
    for (int c2 = 0; c2 < nc; ++c2) {
        int k = cand[c2];
        const float* er = g_En + (size_t)k * EDIM;
        float ck = 0.f, cg = 0.f;
        for (int e = 0; e < SEMD; e += 4) {
            float4 zv = *(const float4*)(zr + e);
            float4 ev = *(const float4*)(er + e);
            ck = fmaf(zv.x, ev.x, ck); ck = fmaf(zv.y, ev.y, ck);
            ck = fmaf(zv.z, ev.z, ck); ck = fmaf(zv.w, ev.w, ck);
        }
        for (int e = SEMD; e < EDIM; e += 4) {
            float4 zv = *(const float4*)(zr + e);
            float4 ev = *(const float4*)(er + e);
            cg = fmaf(zv.x, ev.x, cg); cg = fmaf(zv.y, ev.y, cg);
            cg = fmaf(zv.z, ev.z, cg); cg = fmaf(zv.w, ev.w, cg);
        }
        float d = ((akd + g_bkd[k]) - 2.f * ck) + ((agn + g_bgan[k]) - 2.f * cg);
        ull key = ((ull)__float_as_uint(d) << 32) | (unsigned)k;
        if (key < bkey) bkey = key;
    }
#pragma unroll
    for (int o = 16; o > 0; o >>= 1) {
        ull other = __shfl_xor_sync(0xffffffffu, bkey, o);
        if (other < bkey) bkey = other;
    }
    if (lane == 0) {
        int bi = (int)(unsigned)bkey;
        g_idx[n] = bi;
        out[NQ + 2 + n] = (float)bi;
    }
    if (blockIdx.x == 0 && threadIdx.x < 2) {
        float s = 0.f;
        for (int i = 0; i < 64; ++i) s += g_Spt[threadIdx.x][i];
        out[NQ + threadIdx.x] = s * (1.f / 8192.f);
    }
}

// ---------------- 7. z_q gather ----------------
__global__ void k_zq(float* __restrict__ out) {
    int row0 = blockIdx.x * 64;
    int b = row0 >> 10, l0 = row0 & 1023;
    int lq = threadIdx.x & 63, dg = threadIdx.x >> 6;
    int n = row0 + lq;
    int kidx = g_idx[n];
    const float* Erow = g_En + (size_t)kidx * EDIM;
    const float* Zrow = g_Zn + (size_t)n * EDIM;
#pragma unroll 4
    for (int dit = 0; dit < 128; ++dit) {
        int d = dg * 128 + dit;
        float ev = Erow[d];
        float zn = Zrow[d];
        out[((size_t)b * D_ + d) * L_ + l0 + lq] = zn + (ev - zn);
    }
}

extern "C" void kernel_launch(void* const* d_in, const int* in_sizes, int n_in,
                              void* d_out, int out_size) {
    (void)in_sizes; (void)n_in; (void)out_size;
    const float* z    = (const float*)d_in[0];
    const float* ekd  = (const float*)d_in[1];
    const float* egan = (const float*)d_in[2];
    float* out = (float*)d_out;

    static int inited = 0;
    if (!inited) {
        cudaFuncSetAttribute(k_gemm_mma, cudaFuncAttributeMaxDynamicSharedMemorySize, 4 * STG4);
        inited = 1;
    }

    k_emb<<<KCB / 8, 256>>>(ekd, egan);
    k_zsumsq<<<dim3(4, 8, 8), 256>>>(z);
    k_zfinal<<<NPOS / 256, 256>>>();
    k_ztrans<<<dim3(16, 32, 8), dim3(32, 8)>>>(z);
    k_gemm_mma<<<8192, 256, 4 * STG4>>>();
    k_scan<<<NPOS / 8, 256>>>(out);
    k_zq<<<128, 256>>>(out);
}

// round 8
// speedup vs baseline: 1.4822x; 1.2848x over previous
#include <cuda_runtime.h>
#include <cuda_bf16.h>
#include <cuda_fp16.h>
#include <math.h>
#include <stdint.h>

#define B_    8
#define D_    512
#define L_    1024
#define NPOS  8192
#define KCB   8192
#define EDIM  512
#define SEMD  256
#define NQ    4194304

typedef unsigned long long ull;

// ---------------- scratch ----------------
static __device__ float   g_Zn [NPOS * EDIM];      // exact normalized queries (n, e)
static __device__ char    g_ZnQ[NPOS * EDIM];      // int8 quantized
static __device__ float   g_En [KCB * EDIM];       // exact normalized codes (k, e)
static __device__ char    g_EnQ[KCB * EDIM];       // int8 quantized
static __device__ float g_psum[8][NPOS];
static __device__ float g_pmax[8][NPOS];
static __device__ float g_invk[NPOS], g_invg[NPOS];
static __device__ float g_akd[NPOS],  g_agan[NPOS];
static __device__ float g_bkd[KCB],   g_bgan[KCB];
static __device__ float g_sZk[NPOS], g_sZg[NPOS];  // dequant steps (maxabs/127)
static __device__ float g_sEk[KCB],  g_sEg[KCB];
static __device__ __half g_Dh[(size_t)NPOS * KCB]; // approx dsum fp16, [n][k]
static __device__ unsigned g_keyu[NPOS];
static __device__ float g_Spt[2][64];
static __device__ int   g_idx[NPOS];

// ---------------- helpers ----------------
__device__ __forceinline__ float wsum(float s) {
#pragma unroll
    for (int o = 16; o > 0; o >>= 1) s += __shfl_xor_sync(0xffffffffu, s, o);
    return s;
}
__device__ __forceinline__ float wmax(float s) {
#pragma unroll
    for (int o = 16; o > 0; o >>= 1) s = fmaxf(s, __shfl_xor_sync(0xffffffffu, s, o));
    return s;
}
__device__ __forceinline__ unsigned s2u(const void* p) {
    unsigned a;
    asm("{ .reg .u64 t; cvta.to.shared.u64 t, %1; cvt.u32.u64 %0, t; }" : "=r"(a) : "l"(p));
    return a;
}
__device__ __forceinline__ void cpasync16(unsigned s, const void* g) {
    asm volatile("cp.async.cg.shared.global [%0], [%1], 16;\n" :: "r"(s), "l"(g));
}
__device__ __forceinline__ void ldsm4(unsigned addr, unsigned &r0, unsigned &r1,
                                      unsigned &r2, unsigned &r3) {
    asm volatile("ldmatrix.sync.aligned.m8n8.x4.shared.b16 {%0,%1,%2,%3}, [%4];"
                 : "=r"(r0), "=r"(r1), "=r"(r2), "=r"(r3) : "r"(addr));
}
__device__ __forceinline__ void mma_s8(int* c, unsigned a0, unsigned a1, unsigned a2,
                                       unsigned a3, unsigned b0, unsigned b1) {
    asm volatile("mma.sync.aligned.m16n8k32.row.col.s32.s8.s8.s32 "
                 "{%0,%1,%2,%3}, {%4,%5,%6,%7}, {%8,%9}, {%0,%1,%2,%3};"
                 : "+r"(c[0]), "+r"(c[1]), "+r"(c[2]), "+r"(c[3])
                 : "r"(a0), "r"(a1), "r"(a2), "r"(a3), "r"(b0), "r"(b1));
}

// ---------------- 1. fused prep: emb normalize+quant | z sumsq+maxabs ----------------
__global__ void k_prep(const float* __restrict__ z, const float* __restrict__ ekd,
                       const float* __restrict__ egan) {
    int bid = blockIdx.x;
    if (bid < 1024) {
        // embeddings: one warp per code row
        int w = threadIdx.x >> 5, lane = threadIdx.x & 31;
        int k = bid * 8 + w;
#pragma unroll
        for (int h = 0; h < 2; ++h) {
            const float* p = (h ? egan : ekd) + (size_t)k * SEMD;
            float v[8]; float s = 0.f;
#pragma unroll
            for (int j = 0; j < 8; ++j) { v[j] = p[lane + j * 32]; s += v[j] * v[j]; }
            s = wsum(s);
            float inv = 1.f / fmaxf(sqrtf(s), 1e-12f);
            float nv[8]; float m = 0.f, t = 0.f;
#pragma unroll
            for (int j = 0; j < 8; ++j) {
                nv[j] = v[j] * inv;
                m = fmaxf(m, fabsf(nv[j]));
                t += nv[j] * nv[j];
            }
            m = wmax(m);
            t = wsum(t);
            float qs = 127.f / fmaxf(m, 1e-20f);
#pragma unroll
            for (int j = 0; j < 8; ++j) {
                size_t o = (size_t)k * EDIM + h * SEMD + lane + j * 32;
                g_En[o] = nv[j];
                g_EnQ[o] = (char)__float2int_rn(nv[j] * qs);
            }
            if (lane == 0) {
                if (h) { g_bgan[k] = t; g_sEg[k] = m * (1.f / 127.f); }
                else   { g_bkd[k]  = t; g_sEk[k] = m * (1.f / 127.f); }
            }
        }
    } else {
        int i = bid - 1024;
        int l = (i & 3) * 256 + threadIdx.x;
        int b = (i >> 2) & 7, seg = i >> 5;
        const float* p = z + (size_t)b * D_ * L_ + (size_t)seg * 64 * L_ + l;
        float s = 0.f, m = 0.f;
#pragma unroll 8
        for (int d = 0; d < 64; ++d) {
            float v = p[(size_t)d * L_];
            s += v * v;
            m = fmaxf(m, fabsf(v));
        }
        g_psum[seg][b * L_ + l] = s;
        g_pmax[seg][b * L_ + l] = m;
    }
}

// ---------------- 2. finalize norms + scales + init key/S ----------------
__global__ void k_zfinal() {
    int n = blockIdx.x * 256 + threadIdx.x;
    float s = g_psum[0][n] + g_psum[1][n] + g_psum[2][n] + g_psum[3][n];
    float inv = 1.f / fmaxf(sqrtf(s), 1e-12f);
    g_invk[n] = inv; g_akd[n] = s * inv * inv;
    float mk = fmaxf(fmaxf(g_pmax[0][n], g_pmax[1][n]), fmaxf(g_pmax[2][n], g_pmax[3][n]));
    g_sZk[n] = mk * inv * (1.f / 127.f);
    float s2 = g_psum[4][n] + g_psum[5][n] + g_psum[6][n] + g_psum[7][n];
    float inv2 = 1.f / fmaxf(sqrtf(s2), 1e-12f);
    g_invg[n] = inv2; g_agan[n] = s2 * inv2 * inv2;
    float mg = fmaxf(fmaxf(g_pmax[4][n], g_pmax[5][n]), fmaxf(g_pmax[6][n], g_pmax[7][n]));
    g_sZg[n] = mg * inv2 * (1.f / 127.f);
    g_keyu[n] = 0xFFFFFFFFu;
    if (n < 128) g_Spt[n >> 6][n & 63] = 0.f;
}

// ---------------- 3. transpose + normalize + quantize z ----------------
__global__ void k_ztrans(const float* __restrict__ z) {
    __shared__ float s[32][33];
    int d0 = blockIdx.x * 32, l0 = blockIdx.y * 32, b = blockIdx.z;
    int tx = threadIdx.x, ty = threadIdx.y;
#pragma unroll
    for (int q = 0; q < 4; ++q) {
        int dy = ty * 4 + q;
        s[dy][tx] = z[((size_t)b * D_ + d0 + dy) * L_ + l0 + tx];
    }
    __syncthreads();
    bool kdh = (d0 < SEMD);
#pragma unroll
    for (int q = 0; q < 4; ++q) {
        int lr = ty * 4 + q;
        int n = b * L_ + l0 + lr;
        float inv = kdh ? g_invk[n] : g_invg[n];
        float stp = kdh ? g_sZk[n] : g_sZg[n];
        float v = s[tx][lr] * inv;
        size_t o = (size_t)n * EDIM + d0 + tx;
        g_Zn[o] = v;
        g_ZnQ[o] = (char)__float2int_rn(v / stp);
    }
}

// ---------------- 4. int8 mma GEMM 128x64, chunk=64e, 4-stage, 2 CTAs/SM ----------------
// 8 warps = 4(wm) x 2(wn); warp tile 32x32; stage = A(128*80) + B(64*80) = 15360B
#define STG4 15360
__global__ void __launch_bounds__(256, 2) k_gemm_mma() {
    extern __shared__ char dsm[];
    __shared__ float sRed[2][8];

    const int tid = threadIdx.x, lane = tid & 31, w = tid >> 5;
    const int bid = blockIdx.x;
    const int sup = bid >> 8, loc = bid & 255;
    const int kt = ((sup & 7) << 4) | (loc & 15);
    const int rt = ((sup >> 3) << 4) | (loc >> 4);
    const int row0 = rt * 128, k0 = kt * 64;
    const int wm = w & 3, wn = w >> 2;

    unsigned sbase = s2u(dsm);

    auto load_chunk = [&](int c) {
        int st = c & 3;
        int e0 = c * 64;
        const char* Ag = g_ZnQ + (size_t)row0 * EDIM + e0;
        const char* Bg = g_EnQ + (size_t)k0 * EDIM + e0;
        unsigned ab = sbase + st * STG4;
        unsigned bb = ab + 10240;
#pragma unroll
        for (int i = 0; i < 2; ++i) {
            int q = tid + i * 256; int r = q >> 2, ch = q & 3;
            cpasync16(ab + r * 80 + ch * 16, Ag + (size_t)r * EDIM + ch * 16);
        }
        { int r = tid >> 2, ch = tid & 3;
          cpasync16(bb + r * 80 + ch * 16, Bg + (size_t)r * EDIM + ch * 16); }
        asm volatile("cp.async.commit_group;" ::: "memory");
    };

    int acck[2][4][4], accg[2][4][4];
#pragma unroll
    for (int t = 0; t < 2; ++t)
#pragma unroll
        for (int j = 0; j < 4; ++j)
#pragma unroll
            for (int q = 0; q < 4; ++q) { acck[t][j][q] = 0; accg[t][j][q] = 0; }

    const int lr = lane & 7, lg = lane >> 3;

    auto compute = [&](int st, int (&acc)[2][4][4]) {
        unsigned ab = sbase + st * STG4;
        unsigned bb = ab + 10240;
#pragma unroll
        for (int s = 0; s < 2; ++s) {               // two k32 steps per 64-int8 chunk
            unsigned a0[2], a1[2], a2[2], a3[2];
#pragma unroll
            for (int t = 0; t < 2; ++t) {
                int row = wm * 32 + t * 16 + lr + 8 * (lg & 1);
                int col = s * 16 + 8 * (lg >> 1);   // b16 units (= 2 int8)
                ldsm4(ab + row * 80 + col * 2, a0[t], a1[t], a2[t], a3[t]);
            }
            unsigned bf[4][2];
#pragma unroll
            for (int jp = 0; jp < 2; ++jp) {
                int brow = wn * 32 + (jp * 2 + (lg >> 1)) * 8 + lr;
                int bcol = s * 16 + 8 * (lg & 1);
                ldsm4(bb + brow * 80 + bcol * 2,
                      bf[jp * 2][0], bf[jp * 2][1], bf[jp * 2 + 1][0], bf[jp * 2 + 1][1]);
            }
#pragma unroll
            for (int t = 0; t < 2; ++t)
#pragma unroll
                for (int j = 0; j < 4; ++j)
                    mma_s8(acc[t][j], a0[t], a1[t], a2[t], a3[t], bf[j][0], bf[j][1]);
        }
    };

    load_chunk(0); load_chunk(1); load_chunk(2);
#pragma unroll 1
    for (int c = 0; c < 8; ++c) {                    // 4 kd chunks + 4 gan chunks
        asm volatile("cp.async.wait_group 2;" ::: "memory");
        __syncthreads();
        if (c + 3 < 8) load_chunk(c + 3);
        if (c < 4) compute(c & 3, acck);
        else       compute(c & 3, accg);
    }

    // ---- epilogue ----
    const int lq = lane >> 2, lp = lane & 3;
    const int kb = k0 + wn * 32 + lp * 2;
    float Sk = 0.f, Sg = 0.f;
#pragma unroll
    for (int t = 0; t < 2; ++t) {
        int rA = row0 + wm * 32 + t * 16 + lq;
#pragma unroll
        for (int h = 0; h < 2; ++h) {
            int rr = rA + 8 * h;
            float ak_ = g_akd[rr], ag_ = g_agan[rr];
            float tzk = 2.f * g_sZk[rr], tzg = 2.f * g_sZg[rr];
            unsigned rmin = 0xFFFFFFFFu;
            __half* drow = g_Dh + (size_t)rr * KCB;
#pragma unroll
            for (int j = 0; j < 4; ++j) {
                int kk = kb + j * 8;
                float dk0 = (ak_ + g_bkd[kk])      - tzk * g_sEk[kk]     * (float)acck[t][j][2 * h];
                float dg0 = (ag_ + g_bgan[kk])     - tzg * g_sEg[kk]     * (float)accg[t][j][2 * h];
                float dk1 = (ak_ + g_bkd[kk + 1])  - tzk * g_sEk[kk + 1] * (float)acck[t][j][2 * h + 1];
                float dg1 = (ag_ + g_bgan[kk + 1]) - tzg * g_sEg[kk + 1] * (float)accg[t][j][2 * h + 1];
                Sk = fmaf(dk0, dk0, Sk); Sk = fmaf(dk1, dk1, Sk);
                Sg = fmaf(dg0, dg0, Sg); Sg = fmaf(dg1, dg1, Sg);
                float d0 = dk0 + dg0, d1 = dk1 + dg1;
                rmin = min(rmin, min(__float_as_uint(d0), __float_as_uint(d1)));
                *(__half2*)(drow + kk) = __floats2half2_rn(d0, d1);
            }
            rmin = min(rmin, __shfl_xor_sync(0xffffffffu, rmin, 1));
            rmin = min(rmin, __shfl_xor_sync(0xffffffffu, rmin, 2));
            if (lp == 0) atomicMin(&g_keyu[rr], rmin);
        }
    }
    Sk = wsum(Sk); Sg = wsum(Sg);
    if (lane == 0) { sRed[0][w] = Sk; sRed[1][w] = Sg; }
    __syncthreads();
    if (tid < 2) {
        float s = 0.f;
#pragma unroll
        for (int i = 0; i < 8; ++i) s += sRed[tid][i];
        atomicAdd(&g_Spt[tid][rt], s);
    }
}

// ---------------- 5. scan + exact rescore (warp per query) ----------------
__global__ void k_scan(float* __restrict__ out) {
    int w = threadIdx.x >> 5, lane = threadIdx.x & 31;
    int n = blockIdx.x * 8 + w;
    float th = __uint_as_float(g_keyu[n]) + 5e-2f;
    const __half2* row = (const __half2*)(g_Dh + (size_t)n * KCB);
    int cand[4]; int nc = 0;
#pragma unroll 8
    for (int i = 0; i < 128; ++i) {
        int p = i * 32 + lane;
        float2 fv = __half22float2(row[p]);
        if (fv.x <= th && nc < 4) cand[nc++] = p * 2;
        if (fv.y <= th && nc < 4) cand[nc++] = p * 2 + 1;
    }
    ull bkey = ~0ull;
    float akd = g_akd[n], agn = g_agan[n];
    const float* zr = g_Zn + (size_t)n * EDIM;
    for (int c2 = 0; c2 < nc; ++c2) {
        int k = cand[c2];
        const float* er = g_En + (size_t)k * EDIM;
        float ck = 0.f, cg = 0.f;
        for (int e = 0; e < SEMD; e += 4) {
            float4 zv = *(const float4*)(zr + e);
            float4 ev = *(const float4*)(er + e);
            ck = fmaf(zv.x, ev.x, ck); ck = fmaf(zv.y, ev.y, ck);
            ck = fmaf(zv.z, ev.z, ck); ck = fmaf(zv.w, ev.w, ck);
        }
        for (int e = SEMD; e < EDIM; e += 4) {
            float4 zv = *(const float4*)(zr + e);
            float4 ev = *(const float4*)(er + e);
            cg = fmaf(zv.x, ev.x, cg); cg = fmaf(zv.y, ev.y, cg);
            cg = fmaf(zv.z, ev.z, cg); cg = fmaf(zv.w, ev.w, cg);
        }
        float d = ((akd + g_bkd[k]) - 2.f * ck) + ((agn + g_bgan[k]) - 2.f * cg);
        ull key = ((ull)__float_as_uint(d) << 32) | (unsigned)k;
        if (key < bkey) bkey = key;
    }
#pragma unroll
    for (int o = 16; o > 0; o >>= 1) {
        ull other = __shfl_xor_sync(0xffffffffu, bkey, o);
        if (other < bkey) bkey = other;
    }
    if (lane == 0) {
        int bi = (int)(unsigned)bkey;
        g_idx[n] = bi;
        out[NQ + 2 + n] = (float)bi;
    }
    if (blockIdx.x == 0 && threadIdx.x < 2) {
        float s = 0.f;
        for (int i = 0; i < 64; ++i) s += g_Spt[threadIdx.x][i];
        out[NQ + threadIdx.x] = s * (1.f / 8192.f);
    }
}

// ---------------- 6. z_q gather ----------------
__global__ void k_zq(float* __restrict__ out) {
    int row0 = blockIdx.x * 64;
    int b = row0 >> 10, l0 = row0 & 1023;
    int lq = threadIdx.x & 63, dg = threadIdx.x >> 6;
    int n = row0 + lq;
    int kidx = g_idx[n];
    const float* Erow = g_En + (size_t)kidx * EDIM;
    const float* Zrow = g_Zn + (size_t)n * EDIM;
#pragma unroll 4
    for (int dit = 0; dit < 128; ++dit) {
        int d = dg * 128 + dit;
        float ev = Erow[d];
        float zn = Zrow[d];
        out[((size_t)b * D_ + d) * L_ + l0 + lq] = zn + (ev - zn);
    }
}

extern "C" void kernel_launch(void* const* d_in, const int* in_sizes, int n_in,
                              void* d_out, int out_size) {
    (void)in_sizes; (void)n_in; (void)out_size;
    const float* z    = (const float*)d_in[0];
    const float* ekd  = (const float*)d_in[1];
    const float* egan = (const float*)d_in[2];
    float* out = (float*)d_out;

    static int inited = 0;
    if (!inited) {
        cudaFuncSetAttribute(k_gemm_mma, cudaFuncAttributeMaxDynamicSharedMemorySize, 4 * STG4);
        inited = 1;
    }

    k_prep<<<1024 + 256, 256>>>(z, ekd, egan);
    k_zfinal<<<NPOS / 256, 256>>>();
    k_ztrans<<<dim3(16, 32, 8), dim3(32, 8)>>>(z);
    k_gemm_mma<<<8192, 256, 4 * STG4>>>();
    k_scan<<<NPOS / 8, 256>>>(out);
    k_zq<<<128, 256>>>(out);
}